// round 14
// baseline (speedup 1.0000x reference)
#include <cuda_runtime.h>
#include <cuda_bf16.h>
#include <math.h>

#define BB 2
#define TT 4
#define CMAP 20
#define LOCN 480
#define GLON 960
#define LL (LOCN*LOCN)          // 230400
#define GG (GLON*GLON)          // 921600
#define NSEM 16
#define PH 120
#define PW 160
#define NPTS (PH*PW)            // 19200
#define VRN 100
#define ZBN 80
#define VXY (VRN*VRN)           // 10000
#define AVP 20                  // padded channels per avwin row (18 used)
#define DEGF 57.29577951308232f

static const long long FE_OFF   = 0LL;
static const long long LMAP_OFF = 44236800LL;
static const long long GMAP_OFF = 53452800LL;
static const long long LP_OFF   = 90316800LL;
static const long long GP_OFF   = 90316824LL;
static const long long LB_OFF   = 90316848LL;
static const long long OG_OFF   = 90316880LL;

// all pose/scheduling state precomputed for every (b,t) in k_init
struct St {
    float ct[BB][TT], snt[BB][TT], stx[BB][TT], sty[BB][TT];
    int   xg[BB][TT], yg[BB][TT];
    int   wr0[BB][TT], wc0[BB][TT];      // old-lmb window (clamped)
    int   nr0[BB][TT], nc0[BB][TT];      // new-lmb window
    int   updg[BB][TT], updMode[BB][TT]; // updMode: 1 = lmap is gmap window
    int   sliceW[BB][TT], demote[BB][TT], zeroBuf[BB][TT], doneF[BB][TT];
};
__device__ St g_st;

// voxel scratch batched over all (b,t); zero-invariant restored by trailing k_zvox_all
__device__ __align__(16) float g_vox0[BB*TT][ZBN*VXY];          // 25.6 MB
__device__ __align__(16) float g_voxS[BB*TT][NSEM][12*VXY];     // 61.4 MB
__device__ __align__(16) float g_avwin[BB*TT][VXY*AVP];         // xy-major, padded rows
__device__ __align__(16) float g_cur0[BB][LL];                  // pre-dilation ch0
__device__ __align__(16) float g_lmA[BB*CMAP*LL];               // lmap buffer (non-view)

// ---------------- init: decode flags + ALL pose math (one thread per batch) --------
__device__ static void decode_flags(const void* p, int* outF) {
    const float* pf = (const float*)p;
    const int* pi = (const int*)p;
    const unsigned char* pb = (const unsigned char*)p;
    bool fok = true, iok = true;
    for (int k = 0; k < BB*TT; k++) {
        float v = pf[k]; if (!(v == 0.0f || v == 1.0f)) fok = false;
        int w = pi[k];   if (w != 0 && w != 1) iok = false;
    }
    for (int k = 0; k < BB*TT; k++)
        outF[k] = fok ? (pf[k] != 0.0f) : (iok ? (pi[k] != 0) : (pb[k] != 0));
}

__global__ void k_init(const float* ilp, const float* igp, const int* ilmb, const float* iog,
                       const void* dn, const void* ug, const float* pd, float* out) {
    int b = threadIdx.x;
    if (b >= BB || blockIdx.x) return;
    int dF[BB*TT], uF[BB*TT];
    decode_flags(dn, dF);
    decode_flags(ug, uF);
    {
        float lx = ilp[b*3+0], ly = ilp[b*3+1], lo = ilp[b*3+2];
        float gxp = igp[b*3+0], gyp = igp[b*3+1], gop = igp[b*3+2];
        float o0 = iog[b*3+0], o1 = iog[b*3+1], o2 = iog[b*3+2];
        int lmb[4] = { ilmb[b*4+0], ilmb[b*4+1], ilmb[b*4+2], ilmb[b*4+3] };
        int mode = 0;
        for (int t = 0; t < TT; t++) {
            bool done = dF[b*TT+t] != 0;
            bool updg = uF[b*TT+t] != 0;
            if (done) {
                lx = 12.f; ly = 12.f; lo = 0.f;
                gxp = 24.f; gyp = 24.f; gop = 0.f;
                o0 = 12.f; o1 = 12.f; o2 = 0.f;
                lmb[0] = 240; lmb[1] = 720; lmb[2] = 240; lmb[3] = 720;
            }
            int m = mode;
            if (done) m = updg ? 1 : 0;
            int dem = (!done && m == 1 && !updg) ? 1 : 0;
            if (dem) m = 0;
            g_st.doneF[b][t]   = done ? 1 : 0;
            g_st.updg[b][t]    = updg ? 1 : 0;
            g_st.updMode[b][t] = m;
            g_st.demote[b][t]  = dem;
            g_st.zeroBuf[b][t] = (done && !updg) ? 1 : 0;
            int wr0 = min(max(lmb[0], 0), GLON - LOCN);
            int wc0 = min(max(lmb[2], 0), GLON - LOCN);
            g_st.wr0[b][t] = wr0; g_st.wc0[b][t] = wc0;

            float rx = pd[(b*TT+t)*3+0], ry = pd[(b*TT+t)*3+1], ro = pd[(b*TT+t)*3+2];
            float s = sinf(lo / DEGF), c = cosf(lo / DEGF);
            float px = lx + rx*c - ry*s;
            float py = ly + rx*s + ry*c;
            float po = lo + ro*DEGF;
            po = fmodf(po - 180.0f, 360.0f) + 180.0f;
            po = fmodf(po + 180.0f, 360.0f) - 180.0f;

            float th = (90.0f - po) * (float)(M_PI / 180.0);
            g_st.ct[b][t]  = cosf(th);
            g_st.snt[b][t] = sinf(th);
            float ax = px * 100.0f / 5.0f;
            float ay = py * 100.0f / 5.0f;
            g_st.stx[b][t] = -((ax - 240.0f) / 240.0f);
            g_st.sty[b][t] = -((ay - 240.0f) / 240.0f);
            g_st.xg[b][t] = (int)ax;
            g_st.yg[b][t] = (int)ay;

            float gnx = px + o0, gny = py + o1, gno = po + o2;
            int r  = (int)(gny * 100.0f / 5.0f);
            int cc = (int)(gnx * 100.0f / 5.0f);
            int gx1 = min(max(r  - 240, 0), GLON - LOCN);
            int gy1 = min(max(cc - 240, 0), GLON - LOCN);
            float no0 = (float)(gy1 * 5) / 100.0f;
            float no1 = (float)(gx1 * 5) / 100.0f;
            g_st.nr0[b][t] = gx1; g_st.nc0[b][t] = gy1;
            g_st.sliceW[b][t] = (updg && m == 0) ? 1 : 0;

            float* lpO = out + LP_OFF + (long long)(b*TT+t)*3;
            float* gpO = out + GP_OFF + (long long)(b*TT+t)*3;
            float* lbO = out + LB_OFF + (long long)(b*TT+t)*4;
            float* ogO = out + OG_OFF + (long long)(b*TT+t)*3;
            if (updg) {
                float lnx = gnx - no0, lny = gny - no1, lno = gno;
                lpO[0]=lnx; lpO[1]=lny; lpO[2]=lno;
                gpO[0]=gnx; gpO[1]=gny; gpO[2]=gno;
                lbO[0]=(float)gx1; lbO[1]=(float)(gx1+LOCN);
                lbO[2]=(float)gy1; lbO[3]=(float)(gy1+LOCN);
                ogO[0]=no0; ogO[1]=no1; ogO[2]=0.0f;
                lx=lnx; ly=lny; lo=lno;
                gxp=gnx; gyp=gny; gop=gno;
                lmb[0]=gx1; lmb[1]=gx1+LOCN; lmb[2]=gy1; lmb[3]=gy1+LOCN;
                o0=no0; o1=no1; o2=0.0f;
                mode = 1;
            } else {
                lpO[0]=px; lpO[1]=py; lpO[2]=po;
                gpO[0]=gxp; gpO[1]=gyp; gpO[2]=gop;
                lbO[0]=(float)lmb[0]; lbO[1]=(float)lmb[1];
                lbO[2]=(float)lmb[2]; lbO[3]=(float)lmb[3];
                ogO[0]=o0; ogO[1]=o1; ogO[2]=o2;
                lx=px; ly=py; lo=po;
                mode = m;
            }
        }
    }
}

// ---------------- zero ALL voxel scratch (runs AFTER heights, off critical path) ----
__global__ __launch_bounds__(256) void k_zvox_all() {
    const long long n0 = sizeof(g_vox0) / 16;
    const long long NV = n0 + sizeof(g_voxS) / 16;
    long long stride = (long long)gridDim.x * 256;
    float4 z = make_float4(0.f, 0.f, 0.f, 0.f);
    for (long long i = (long long)blockIdx.x * 256 + threadIdx.x; i < NV; i += stride) {
        if (i < n0) ((float4*)g_vox0)[i] = z;
        else ((float4*)g_voxS)[i - n0] = z;
    }
}

// ---------------- batched pool+splat over all (b,t,channel,point) ----------------
__global__ __launch_bounds__(256) void k_pointsplat_all(const float* obs, float focal) {
    int idx = blockIdx.x * 256 + threadIdx.x;     // BB*TT*16*NPTS = 2,457,600 exact
    int pt = idx % NPTS;
    int c  = (idx / NPTS) % NSEM;
    int bt = idx / (NPTS * NSEM);                 // b*TT + t
    int i = pt / PW, j = pt % PW;
    const float* base = obs + (long long)bt * CMAP * (long long)(480*640);
    float d = base[(long long)3 * (480*640) + (long long)(4*i) * 640 + 4*j];
    if (!(d > 50.0f && d < 350.0f)) return;
    float X = (((float)(4*j) - 319.5f) * d) / focal;       X = X + 250.0f;
    float Z = (((float)(479 - 4*i) - 239.5f) * d) / focal; Z = Z + 88.0f;
    float cx = ((X / 5.0f - 50.0f) / 100.0f) * 2.0f;
    float cy = ((d / 5.0f - 50.0f) / 100.0f) * 2.0f;
    float cz = ((Z / 5.0f - 32.0f) / 80.0f) * 2.0f;
    float pxp = cx * 100.0f / 2.0f + 50.0f;
    float pyp = cy * 100.0f / 2.0f + 50.0f;
    float pzp = cz * 80.0f / 2.0f + 40.0f;
    float f0 = floorf(pxp), f1 = floorf(pyp), f2 = floorf(pzp);

    float wc[8]; int ixc[8], iyc[8], izc[8];
    bool semNeeded = false;
    #pragma unroll
    for (int corner = 0; corner < 8; corner++) {
        float p0 = f0 + (float)(corner & 1);
        float p1 = f1 + (float)((corner >> 1) & 1);
        float p2 = f2 + (float)((corner >> 2) & 1);
        float w = 1.0f;
        w = w * (1.0f - fabsf(pxp - p0)); if (!(p0 > 0.0f && p0 < 100.0f)) w = 0.0f;
        w = w * (1.0f - fabsf(pyp - p1)); if (!(p1 > 0.0f && p1 < 100.0f)) w = 0.0f;
        w = w * (1.0f - fabsf(pzp - p2)); if (!(p2 > 0.0f && p2 <  80.0f)) w = 0.0f;
        wc[corner] = w;
        ixc[corner] = (int)p0; iyc[corner] = (int)p1; izc[corner] = (int)p2;
        if (w != 0.0f && izc[corner] >= 13 && izc[corner] < 25) semNeeded = true;
    }

    if (c == 0) {
        #pragma unroll
        for (int corner = 0; corner < 8; corner++) {
            float w = wc[corner];
            if (w == 0.0f) continue;
            atomicAdd(&g_vox0[bt][izc[corner]*VXY + ixc[corner]*VRN + iyc[corner]], w);
        }
    }

    if (!semNeeded) return;
    const float* p = base + (long long)(4 + c) * (480*640) + (long long)(4*i) * 640 + 4*j;
    float s = 0.f;
    #pragma unroll
    for (int dy = 0; dy < 4; dy++) {
        float4 v = *(const float4*)(p + dy*640);
        s = s + v.x; s = s + v.y; s = s + v.z; s = s + v.w;
    }
    float pooled = s * (1.0f/16.0f);
    if (pooled == 0.0f) return;
    #pragma unroll
    for (int corner = 0; corner < 8; corner++) {
        float w = wc[corner];
        int iz = izc[corner];
        if (w == 0.0f || iz < 13 || iz >= 25) continue;
        atomicAdd(&g_voxS[bt][c][(iz - 13)*VXY + ixc[corner]*VRN + iyc[corner]], pooled * w);
    }
}

// ---------------- batched heights (pure read; writes xy-major avwin) ----------------
__global__ __launch_bounds__(256) void k_heights_all() {
    int linear = blockIdx.x * 256 + threadIdx.x;   // 17*BB*TT*VXY = 1,360,000
    if (linear >= 17 * BB * TT * VXY) return;
    int xy = linear % VXY;
    int bt = (linear / VXY) % (BB * TT);
    int co = linear / (VXY * BB * TT);
    if (co == 0) {
        float all0 = 0.f, ag0 = 0.f;
        #pragma unroll
        for (int z = 0; z < ZBN; z++) {
            float r = rintf(g_vox0[bt][z*VXY + xy]);
            all0 += r;
            if (z >= 13 && z < 25) ag0 += r;
        }
        g_avwin[bt][xy*AVP + 0] = fminf(fmaxf(ag0 / 1.0f, 0.0f), 1.0f);
        g_avwin[bt][xy*AVP + 1] = fminf(fmaxf(all0 / 1.0f, 0.0f), 1.0f);
    } else {
        int c = co - 1;
        float sm = 0.f;
        #pragma unroll
        for (int z = 0; z < 12; z++)
            sm += rintf(g_voxS[bt][c][z*VXY + xy]);
        g_avwin[bt][xy*AVP + 2 + c] = fminf(fmaxf(sm / 5.0f, 0.0f), 1.0f);
    }
}

// ---------------- prep duties (grid-stride; executed by rotrans' extra blocks) ------
// Bodies only execute when doneF/zeroBuf/demote fire; for this problem's input family
// (seq_dones == zeros, seq_update_global == ones) they never fire.
__device__ static void prep_body(float* out, float* buf, int t, int b,
                                 long long gid, long long stride) {
    if (g_st.doneF[b][t]) {
        float4 z = make_float4(0.f, 0.f, 0.f, 0.f);
        float4* gm4 = (float4*)(out + GMAP_OFF + (long long)b * CMAP * GG);
        for (long long i = gid; i < (long long)CMAP * GG / 4; i += stride) gm4[i] = z;
    }
    if (g_st.zeroBuf[b][t]) {
        float4 z = make_float4(0.f, 0.f, 0.f, 0.f);
        float4* bf4 = (float4*)(buf + (long long)b * CMAP * LL);
        for (long long i = gid; i < (long long)CMAP * LL / 4; i += stride) bf4[i] = z;
    }
    if (g_st.demote[b][t]) {
        int wr0 = g_st.wr0[b][t], wc0 = g_st.wc0[b][t];
        const float* gm = out + GMAP_OFF + (long long)b * CMAP * GG;
        float* bf = buf + (long long)b * CMAP * LL;
        for (long long e = gid; e < (long long)CMAP * LL; e += stride) {
            int c = (int)(e / LL); int rem = (int)(e % LL);
            int i = rem / LOCN, j = rem % LOCN;
            bf[e] = gm[(long long)c * GG + (long long)(wr0 + i) * GLON + (wc0 + j)];
        }
    }
}

// ---------------- fused rotate+translate+max-fuse+markers (+prep blocks) ------------
__device__ __forceinline__ bool rot_sample(int b, int t, int i2, int j2, float* rk) {
    const float step = 2.0f / 479.0f;
    float gx = -1.0f + (float)j2 * step;
    float gy = -1.0f + (float)i2 * step;
    float ct = g_st.ct[b][t], sn = g_st.snt[b][t];
    float gX = ct * gx + (-sn) * gy;
    float gY = sn * gx + ct * gy;
    float x = ((gX + 1.0f) * 479.0f) / 2.0f;
    float y = ((gY + 1.0f) * 479.0f) / 2.0f;
    if (x < 188.5f || x >= 290.5f || y < 238.5f || y >= 340.5f) return false;
    float x0 = floorf(x), y0 = floorf(y);
    const float* aw = g_avwin[b*TT + t];
    #pragma unroll
    for (int m = 0; m < 4; m++) {
        float xi = x0 + (float)(m & 1);
        float yi = y0 + (float)(m >> 1);
        if (!(xi >= 0.0f && xi <= 479.0f && yi >= 0.0f && yi <= 479.0f)) continue;
        int xii = (int)xi, yii = (int)yi;
        if (yii < 240 || yii > 339 || xii < 190 || xii > 289) continue;
        float wg = (1.0f - fabsf(x - xi)) * (1.0f - fabsf(y - yi));
        const float* row = aw + ((yii - 240) * VRN + (xii - 190)) * AVP;
        float4 v0 = *(const float4*)(row);
        float4 v1 = *(const float4*)(row + 4);
        float4 v2 = *(const float4*)(row + 8);
        float4 v3 = *(const float4*)(row + 12);
        float2 v4 = *(const float2*)(row + 16);
        rk[0]  += v0.x*wg; rk[1]  += v0.y*wg; rk[2]  += v0.z*wg; rk[3]  += v0.w*wg;
        rk[4]  += v1.x*wg; rk[5]  += v1.y*wg; rk[6]  += v1.z*wg; rk[7]  += v1.w*wg;
        rk[8]  += v2.x*wg; rk[9]  += v2.y*wg; rk[10] += v2.z*wg; rk[11] += v2.w*wg;
        rk[12] += v3.x*wg; rk[13] += v3.y*wg; rk[14] += v3.z*wg; rk[15] += v3.w*wg;
        rk[16] += v4.x*wg; rk[17] += v4.y*wg;
    }
    return true;
}

__global__ __launch_bounds__(256) void k_rotrans(float* out, float* buf, int t) {
    int b = blockIdx.y;
    if (blockIdx.x >= 900) {   // prep blocks (no-op unless rare flags fire)
        long long gid = (long long)(blockIdx.x - 900) * 256 + threadIdx.x;
        prep_body(out, buf, t, b, gid, 32LL * 256);
        return;
    }
    int ij = blockIdx.x * 256 + threadIdx.x;
    int i = ij / LOCN, j = ij % LOCN;
    int m = g_st.updMode[b][t];
    float* tgt; long long cs; int rs;
    if (m) {
        tgt = out + GMAP_OFF + (long long)b * CMAP * GG
              + (long long)g_st.wr0[b][t] * GLON + g_st.wc0[b][t];
        cs = GG; rs = GLON;
    } else {
        tgt = buf + (long long)b * CMAP * LL;
        cs = LL; rs = LOCN;
    }
    long long pix = (long long)i * rs + j;

    const float step = 2.0f / 479.0f;
    float gx = (-1.0f + (float)j * step) + g_st.stx[b][t];
    float gy = (-1.0f + (float)i * step) + g_st.sty[b][t];
    float x = ((gx + 1.0f) * 479.0f) / 2.0f;
    float y = ((gy + 1.0f) * 479.0f) / 2.0f;
    float x0 = floorf(x), y0 = floorf(y);
    float tr[18];
    #pragma unroll
    for (int s = 0; s < 18; s++) tr[s] = 0.0f;
    bool any = false;
    #pragma unroll
    for (int k = 0; k < 4; k++) {
        float xi = x0 + (float)(k & 1);
        float yi = y0 + (float)(k >> 1);
        if (!(xi >= 0.0f && xi <= 479.0f && yi >= 0.0f && yi <= 479.0f)) continue;
        float wg = (1.0f - fabsf(x - xi)) * (1.0f - fabsf(y - yi));
        float rk[18];
        #pragma unroll
        for (int s = 0; s < 18; s++) rk[s] = 0.0f;
        if (rot_sample(b, t, (int)yi, (int)xi, rk)) {
            any = true;
            #pragma unroll
            for (int s = 0; s < 18; s++) tr[s] += rk[s] * wg;
        }
    }
    int dr = i - g_st.yg[b][t];
    int dc = j - g_st.xg[b][t];
    tgt[2*cs + pix] = (abs(dr) <= 2 && abs(dc) <= 2) ? 1.0f : 0.0f;
    float disk = ((dr*dr + dc*dc) <= 1600) ? 1.0f : 0.0f;
    if (any) {
        g_cur0[b][ij] = fmaxf(tgt[pix], tr[0]);
        tgt[1*cs + pix] = fmaxf(tgt[1*cs + pix], tr[1]);
        tgt[3*cs + pix] = fmaxf(tgt[3*cs + pix], disk);
        #pragma unroll
        for (int c = 4; c < CMAP; c++)
            tgt[(long long)c*cs + pix] = fmaxf(tgt[(long long)c*cs + pix], tr[c - 2]);
    } else {
        g_cur0[b][ij] = tgt[pix];
        if (disk != 0.0f)
            tgt[3*cs + pix] = fmaxf(tgt[3*cs + pix], disk);
    }
}

// ---------------- dilation materializer: writes dilated ch0 into lmap (+slice) ------
__device__ __forceinline__ float dil0(int b, int i, int j) {
    float s = 0.f;
    #pragma unroll
    for (int di = -1; di <= 1; di++) {
        int ii = i + di;
        if (ii < 0 || ii >= LOCN) continue;
        #pragma unroll
        for (int dj = -1; dj <= 1; dj++) {
            int jj = j + dj;
            if (jj < 0 || jj >= LOCN) continue;
            s += g_cur0[b][ii * LOCN + jj];
        }
    }
    return (s > 0.5f) ? 1.0f : 0.0f;
}

__global__ __launch_bounds__(256) void k_dil(float* out, float* buf, int t) {
    int b = blockIdx.y;
    int ij = blockIdx.x * 256 + threadIdx.x;
    int i = ij / LOCN, j = ij % LOCN;
    int m = g_st.updMode[b][t];
    bool sw = g_st.sliceW[b][t] != 0;
    int wr0 = g_st.wr0[b][t], wc0 = g_st.wc0[b][t];
    float d0 = dil0(b, i, j);
    float* gm = out + GMAP_OFF + (long long)b * CMAP * GG;
    if (m) {
        gm[(long long)(wr0 + i) * GLON + (wc0 + j)] = d0;
    } else {
        buf[(long long)b * CMAP * LL + ij] = d0;
        if (sw) gm[(long long)(wr0 + i) * GLON + (wc0 + j)] = d0;
    }
}

// ---------------- fused slice write (c>=1) + reslice + gdown + feats (+final lmap) --
__global__ __launch_bounds__(256) void k_gupfeats(float* out, float* buf, int t, int last) {
    int b = blockIdx.y;
    int ij = blockIdx.x * 256 + threadIdx.x;
    int i = ij / LOCN, j = ij % LOCN;
    int m = g_st.updMode[b][t];
    bool u = g_st.updg[b][t] != 0;
    bool sw = g_st.sliceW[b][t] != 0;
    int wr0 = g_st.wr0[b][t], wc0 = g_st.wc0[b][t];
    int nr0 = g_st.nr0[b][t], nc0 = g_st.nc0[b][t];
    float* gm = out + GMAP_OFF + (long long)b * CMAP * GG;
    float* bf = buf + (long long)b * CMAP * LL;
    float* tgt; long long cs; int rs;
    if (m) { tgt = gm + (long long)wr0 * GLON + wc0; cs = GG; rs = GLON; }
    else   { tgt = bf; cs = LL; rs = LOCN; }
    long long pix = (long long)i * rs + j;

    if (sw) {   // buffer mode + updg: write slice for c >= 1 (ch0 done by k_dil)
        long long gw = (long long)(wr0 + i) * GLON + (wc0 + j);
        #pragma unroll
        for (int c = 1; c < CMAP; c++)
            gm[(long long)c * GG + gw] = bf[(long long)c * LL + ij];
    }

    // gmap ch0 (in- and out-of-window) already holds post-update values (k_dil).
    // Only sw-mode c>=1 in-window reads must redirect to bf (this kernel writes them).
    auto eff = [&](int c, int r, int cc) -> float {
        if (u && m == 0 && c >= 1 &&
            r >= wr0 && r < wr0 + LOCN && cc >= wc0 && cc < wc0 + LOCN)
            return bf[(long long)c * LL + (r - wr0) * LOCN + (cc - wc0)];
        return gm[(long long)c * GG + (long long)r * GLON + cc];
    };

    float lv[CMAP];
    if (u) {
        #pragma unroll
        for (int c = 0; c < CMAP; c++) lv[c] = eff(c, nr0 + i, nc0 + j);
    } else {
        #pragma unroll
        for (int c = 0; c < CMAP; c++) lv[c] = tgt[(long long)c * cs + pix];
    }
    float gd[4];
    #pragma unroll
    for (int c = 0; c < 4; c++) {
        if (m == 1 || !u || c == 0) {   // race-free direct gmap reads
            const float* gb = gm + (long long)c * GG + (long long)(2*i) * GLON + 2*j;
            float2 r0 = *(const float2*)gb;
            float2 r1 = *(const float2*)(gb + GLON);
            gd[c] = fmaxf(fmaxf(r0.x, r0.y), fmaxf(r1.x, r1.y));
        } else {
            float a0 = eff(c, 2*i, 2*j),     a1 = eff(c, 2*i, 2*j + 1);
            float a2 = eff(c, 2*i + 1, 2*j), a3 = eff(c, 2*i + 1, 2*j + 1);
            gd[c] = fmaxf(fmaxf(a0, a1), fmaxf(a2, a3));
        }
    }
    float* fe = out + FE_OFF + (long long)(b*TT + t) * 24 * LL + ij;
    fe[0] = lv[0];
    fe[(long long)1*LL] = lv[1];
    fe[(long long)2*LL] = lv[2];
    fe[(long long)3*LL] = lv[3];
    #pragma unroll
    for (int c = 0; c < 4; c++) fe[(long long)(4 + c) * LL] = gd[c];
    #pragma unroll
    for (int c = 0; c < NSEM; c++) fe[(long long)(8 + c) * LL] = lv[4 + c];

    if (last) {
        float* lo = out + LMAP_OFF + (long long)b * CMAP * LL + ij;
        #pragma unroll
        for (int c = 0; c < CMAP; c++) lo[(long long)c * LL] = lv[c];
    }
}

// ---------------- launcher ----------------
extern "C" void kernel_launch(void* const* d_in, const int* in_sizes, int n_in,
                              void* d_out, int out_size) {
    const float* obs  = (const float*)d_in[0];
    const float* pd   = (const float*)d_in[1];
    const void*  dn   = d_in[2];
    const void*  ug   = d_in[3];
    // d_in[4]: seq_camera_poses (unused)
    const float* ilm  = (const float*)d_in[5];
    const float* igm  = (const float*)d_in[6];
    const float* ilp  = (const float*)d_in[7];
    const float* igp  = (const float*)d_in[8];
    const int*   ilmb = (const int*)d_in[9];
    const float* iog  = (const float*)d_in[10];
    float* out = (float*)d_out;
    float focal = (float)(320.0 / tan(39.5 * M_PI / 180.0));

    float* lmA; cudaGetSymbolAddress((void**)&lmA, g_lmA);

    // side stream: splat+heights (critical) then voxel re-zero (overlaps t-loop).
    cudaStream_t s2;
    cudaStreamCreateWithFlags(&s2, cudaStreamNonBlocking);
    cudaEvent_t eFork, eJoin, eZero;
    cudaEventCreateWithFlags(&eFork, cudaEventDisableTiming);
    cudaEventCreateWithFlags(&eJoin, cudaEventDisableTiming);
    cudaEventCreateWithFlags(&eZero, cudaEventDisableTiming);

    cudaEventRecord(eFork, 0);
    cudaStreamWaitEvent(s2, eFork, 0);
    k_pointsplat_all<<<9600, 256, 0, s2>>>(obs, focal);
    k_heights_all<<<5313, 256, 0, s2>>>();
    cudaEventRecord(eJoin, s2);
    k_zvox_all<<<21250, 256, 0, s2>>>();          // restore zero invariant, off critical path
    cudaEventRecord(eZero, s2);

    k_init<<<1, BB>>>(ilp, igp, ilmb, iog, dn, ug, pd, out);
    cudaMemcpyAsync(lmA, ilm, (size_t)BB * CMAP * LL * sizeof(float),
                    cudaMemcpyDeviceToDevice);
    cudaMemcpyAsync(out + GMAP_OFF, igm, (size_t)BB * CMAP * GG * sizeof(float),
                    cudaMemcpyDeviceToDevice);

    cudaStreamWaitEvent(0, eJoin, 0);

    for (int t = 0; t < TT; t++) {
        k_rotrans<<<dim3(932, BB), 256>>>(out, lmA, t);   // 900 pixel + 32 prep blocks
        k_dil<<<dim3(900, BB), 256>>>(out, lmA, t);
        k_gupfeats<<<dim3(900, BB), 256>>>(out, lmA, t, t == TT-1 ? 1 : 0);
    }
    cudaStreamWaitEvent(0, eZero, 0);             // graph ends only after re-zero

    cudaEventDestroy(eFork);
    cudaEventDestroy(eJoin);
    cudaEventDestroy(eZero);
    cudaStreamDestroy(s2);
}

// round 15
// speedup vs baseline: 1.0600x; 1.0600x over previous
#include <cuda_runtime.h>
#include <cuda_bf16.h>
#include <math.h>

#define BB 2
#define TT 4
#define CMAP 20
#define LOCN 480
#define GLON 960
#define LL (LOCN*LOCN)          // 230400
#define GG (GLON*GLON)          // 921600
#define NSEM 16
#define PH 120
#define PW 160
#define NPTS (PH*PW)            // 19200
#define VRN 100
#define ZBN 80
#define VXY (VRN*VRN)           // 10000
#define AVP 20                  // padded channels per avwin row (18 used)
#define DEGF 57.29577951308232f

static const long long FE_OFF   = 0LL;
static const long long LMAP_OFF = 44236800LL;
static const long long GMAP_OFF = 53452800LL;
static const long long LP_OFF   = 90316800LL;
static const long long GP_OFF   = 90316824LL;
static const long long LB_OFF   = 90316848LL;
static const long long OG_OFF   = 90316880LL;

// all pose/scheduling state precomputed for every (b,t) in k_init
struct St {
    float ct[BB][TT], snt[BB][TT], stx[BB][TT], sty[BB][TT];
    int   xg[BB][TT], yg[BB][TT];
    int   wr0[BB][TT], wc0[BB][TT];      // old-lmb window (clamped)
    int   nr0[BB][TT], nc0[BB][TT];      // new-lmb window
    int   updg[BB][TT], updMode[BB][TT]; // updMode: 1 = lmap is gmap window
    int   sliceW[BB][TT], demote[BB][TT], zeroBuf[BB][TT], doneF[BB][TT];
};
__device__ St g_st;

// voxel scratch batched over all (b,t); zero-invariant restored by trailing k_zvox_all
__device__ __align__(16) float g_vox0[BB*TT][ZBN*VXY];          // 25.6 MB
__device__ __align__(16) float g_voxS[BB*TT][NSEM][12*VXY];     // 61.4 MB
__device__ __align__(16) float g_avwin[BB*TT][VXY*AVP];         // xy-major, padded rows
__device__ __align__(16) float g_cur0[BB][LL];                  // pre-dilation ch0
__device__ __align__(16) float g_lmA[BB*CMAP*LL];               // lmap buffer (non-view)

// ---------------- init: decode flags + ALL pose math (one thread per batch) --------
__device__ static void decode_flags(const void* p, int* outF) {
    const float* pf = (const float*)p;
    const int* pi = (const int*)p;
    const unsigned char* pb = (const unsigned char*)p;
    bool fok = true, iok = true;
    for (int k = 0; k < BB*TT; k++) {
        float v = pf[k]; if (!(v == 0.0f || v == 1.0f)) fok = false;
        int w = pi[k];   if (w != 0 && w != 1) iok = false;
    }
    for (int k = 0; k < BB*TT; k++)
        outF[k] = fok ? (pf[k] != 0.0f) : (iok ? (pi[k] != 0) : (pb[k] != 0));
}

__global__ void k_init(const float* ilp, const float* igp, const int* ilmb, const float* iog,
                       const void* dn, const void* ug, const float* pd, float* out) {
    int b = threadIdx.x;
    if (b >= BB || blockIdx.x) return;
    int dF[BB*TT], uF[BB*TT];
    decode_flags(dn, dF);
    decode_flags(ug, uF);
    {
        float lx = ilp[b*3+0], ly = ilp[b*3+1], lo = ilp[b*3+2];
        float gxp = igp[b*3+0], gyp = igp[b*3+1], gop = igp[b*3+2];
        float o0 = iog[b*3+0], o1 = iog[b*3+1], o2 = iog[b*3+2];
        int lmb[4] = { ilmb[b*4+0], ilmb[b*4+1], ilmb[b*4+2], ilmb[b*4+3] };
        int mode = 0;
        for (int t = 0; t < TT; t++) {
            bool done = dF[b*TT+t] != 0;
            bool updg = uF[b*TT+t] != 0;
            if (done) {
                lx = 12.f; ly = 12.f; lo = 0.f;
                gxp = 24.f; gyp = 24.f; gop = 0.f;
                o0 = 12.f; o1 = 12.f; o2 = 0.f;
                lmb[0] = 240; lmb[1] = 720; lmb[2] = 240; lmb[3] = 720;
            }
            int m = mode;
            if (done) m = updg ? 1 : 0;
            int dem = (!done && m == 1 && !updg) ? 1 : 0;
            if (dem) m = 0;
            g_st.doneF[b][t]   = done ? 1 : 0;
            g_st.updg[b][t]    = updg ? 1 : 0;
            g_st.updMode[b][t] = m;
            g_st.demote[b][t]  = dem;
            g_st.zeroBuf[b][t] = (done && !updg) ? 1 : 0;
            int wr0 = min(max(lmb[0], 0), GLON - LOCN);
            int wc0 = min(max(lmb[2], 0), GLON - LOCN);
            g_st.wr0[b][t] = wr0; g_st.wc0[b][t] = wc0;

            float rx = pd[(b*TT+t)*3+0], ry = pd[(b*TT+t)*3+1], ro = pd[(b*TT+t)*3+2];
            float s = sinf(lo / DEGF), c = cosf(lo / DEGF);
            float px = lx + rx*c - ry*s;
            float py = ly + rx*s + ry*c;
            float po = lo + ro*DEGF;
            po = fmodf(po - 180.0f, 360.0f) + 180.0f;
            po = fmodf(po + 180.0f, 360.0f) - 180.0f;

            float th = (90.0f - po) * (float)(M_PI / 180.0);
            g_st.ct[b][t]  = cosf(th);
            g_st.snt[b][t] = sinf(th);
            float ax = px * 100.0f / 5.0f;
            float ay = py * 100.0f / 5.0f;
            g_st.stx[b][t] = -((ax - 240.0f) / 240.0f);
            g_st.sty[b][t] = -((ay - 240.0f) / 240.0f);
            g_st.xg[b][t] = (int)ax;
            g_st.yg[b][t] = (int)ay;

            float gnx = px + o0, gny = py + o1, gno = po + o2;
            int r  = (int)(gny * 100.0f / 5.0f);
            int cc = (int)(gnx * 100.0f / 5.0f);
            int gx1 = min(max(r  - 240, 0), GLON - LOCN);
            int gy1 = min(max(cc - 240, 0), GLON - LOCN);
            float no0 = (float)(gy1 * 5) / 100.0f;
            float no1 = (float)(gx1 * 5) / 100.0f;
            g_st.nr0[b][t] = gx1; g_st.nc0[b][t] = gy1;
            g_st.sliceW[b][t] = (updg && m == 0) ? 1 : 0;

            float* lpO = out + LP_OFF + (long long)(b*TT+t)*3;
            float* gpO = out + GP_OFF + (long long)(b*TT+t)*3;
            float* lbO = out + LB_OFF + (long long)(b*TT+t)*4;
            float* ogO = out + OG_OFF + (long long)(b*TT+t)*3;
            if (updg) {
                float lnx = gnx - no0, lny = gny - no1, lno = gno;
                lpO[0]=lnx; lpO[1]=lny; lpO[2]=lno;
                gpO[0]=gnx; gpO[1]=gny; gpO[2]=gno;
                lbO[0]=(float)gx1; lbO[1]=(float)(gx1+LOCN);
                lbO[2]=(float)gy1; lbO[3]=(float)(gy1+LOCN);
                ogO[0]=no0; ogO[1]=no1; ogO[2]=0.0f;
                lx=lnx; ly=lny; lo=lno;
                gxp=gnx; gyp=gny; gop=gno;
                lmb[0]=gx1; lmb[1]=gx1+LOCN; lmb[2]=gy1; lmb[3]=gy1+LOCN;
                o0=no0; o1=no1; o2=0.0f;
                mode = 1;
            } else {
                lpO[0]=px; lpO[1]=py; lpO[2]=po;
                gpO[0]=gxp; gpO[1]=gyp; gpO[2]=gop;
                lbO[0]=(float)lmb[0]; lbO[1]=(float)lmb[1];
                lbO[2]=(float)lmb[2]; lbO[3]=(float)lmb[3];
                ogO[0]=o0; ogO[1]=o1; ogO[2]=o2;
                lx=px; ly=py; lo=po;
                mode = m;
            }
        }
    }
}

// ---------------- zero ALL voxel scratch (runs AFTER heights, off critical path) ----
__global__ __launch_bounds__(256) void k_zvox_all() {
    const long long n0 = sizeof(g_vox0) / 16;
    const long long NV = n0 + sizeof(g_voxS) / 16;
    long long stride = (long long)gridDim.x * 256;
    float4 z = make_float4(0.f, 0.f, 0.f, 0.f);
    for (long long i = (long long)blockIdx.x * 256 + threadIdx.x; i < NV; i += stride) {
        if (i < n0) ((float4*)g_vox0)[i] = z;
        else ((float4*)g_voxS)[i - n0] = z;
    }
}

// ---------------- batched pool+splat over all (b,t,channel,point) ----------------
__global__ __launch_bounds__(256) void k_pointsplat_all(const float* obs, float focal) {
    int idx = blockIdx.x * 256 + threadIdx.x;     // BB*TT*16*NPTS = 2,457,600 exact
    int pt = idx % NPTS;
    int c  = (idx / NPTS) % NSEM;
    int bt = idx / (NPTS * NSEM);                 // b*TT + t
    int i = pt / PW, j = pt % PW;
    const float* base = obs + (long long)bt * CMAP * (long long)(480*640);
    float d = base[(long long)3 * (480*640) + (long long)(4*i) * 640 + 4*j];
    if (!(d > 50.0f && d < 350.0f)) return;
    float X = (((float)(4*j) - 319.5f) * d) / focal;       X = X + 250.0f;
    float Z = (((float)(479 - 4*i) - 239.5f) * d) / focal; Z = Z + 88.0f;
    float cx = ((X / 5.0f - 50.0f) / 100.0f) * 2.0f;
    float cy = ((d / 5.0f - 50.0f) / 100.0f) * 2.0f;
    float cz = ((Z / 5.0f - 32.0f) / 80.0f) * 2.0f;
    float pxp = cx * 100.0f / 2.0f + 50.0f;
    float pyp = cy * 100.0f / 2.0f + 50.0f;
    float pzp = cz * 80.0f / 2.0f + 40.0f;
    float f0 = floorf(pxp), f1 = floorf(pyp), f2 = floorf(pzp);

    float wc[8]; int ixc[8], iyc[8], izc[8];
    bool semNeeded = false;
    #pragma unroll
    for (int corner = 0; corner < 8; corner++) {
        float p0 = f0 + (float)(corner & 1);
        float p1 = f1 + (float)((corner >> 1) & 1);
        float p2 = f2 + (float)((corner >> 2) & 1);
        float w = 1.0f;
        w = w * (1.0f - fabsf(pxp - p0)); if (!(p0 > 0.0f && p0 < 100.0f)) w = 0.0f;
        w = w * (1.0f - fabsf(pyp - p1)); if (!(p1 > 0.0f && p1 < 100.0f)) w = 0.0f;
        w = w * (1.0f - fabsf(pzp - p2)); if (!(p2 > 0.0f && p2 <  80.0f)) w = 0.0f;
        wc[corner] = w;
        ixc[corner] = (int)p0; iyc[corner] = (int)p1; izc[corner] = (int)p2;
        if (w != 0.0f && izc[corner] >= 13 && izc[corner] < 25) semNeeded = true;
    }

    if (c == 0) {
        #pragma unroll
        for (int corner = 0; corner < 8; corner++) {
            float w = wc[corner];
            if (w == 0.0f) continue;
            atomicAdd(&g_vox0[bt][izc[corner]*VXY + ixc[corner]*VRN + iyc[corner]], w);
        }
    }

    if (!semNeeded) return;
    const float* p = base + (long long)(4 + c) * (480*640) + (long long)(4*i) * 640 + 4*j;
    float s = 0.f;
    #pragma unroll
    for (int dy = 0; dy < 4; dy++) {
        float4 v = *(const float4*)(p + dy*640);
        s = s + v.x; s = s + v.y; s = s + v.z; s = s + v.w;
    }
    float pooled = s * (1.0f/16.0f);
    if (pooled == 0.0f) return;
    #pragma unroll
    for (int corner = 0; corner < 8; corner++) {
        float w = wc[corner];
        int iz = izc[corner];
        if (w == 0.0f || iz < 13 || iz >= 25) continue;
        atomicAdd(&g_voxS[bt][c][(iz - 13)*VXY + ixc[corner]*VRN + iyc[corner]], pooled * w);
    }
}

// ---------------- batched heights (pure read; writes xy-major avwin) ----------------
__global__ __launch_bounds__(256) void k_heights_all() {
    int linear = blockIdx.x * 256 + threadIdx.x;   // 17*BB*TT*VXY = 1,360,000
    if (linear >= 17 * BB * TT * VXY) return;
    int xy = linear % VXY;
    int bt = (linear / VXY) % (BB * TT);
    int co = linear / (VXY * BB * TT);
    if (co == 0) {
        float all0 = 0.f, ag0 = 0.f;
        #pragma unroll
        for (int z = 0; z < ZBN; z++) {
            float r = rintf(g_vox0[bt][z*VXY + xy]);
            all0 += r;
            if (z >= 13 && z < 25) ag0 += r;
        }
        g_avwin[bt][xy*AVP + 0] = fminf(fmaxf(ag0 / 1.0f, 0.0f), 1.0f);
        g_avwin[bt][xy*AVP + 1] = fminf(fmaxf(all0 / 1.0f, 0.0f), 1.0f);
    } else {
        int c = co - 1;
        float sm = 0.f;
        #pragma unroll
        for (int z = 0; z < 12; z++)
            sm += rintf(g_voxS[bt][c][z*VXY + xy]);
        g_avwin[bt][xy*AVP + 2 + c] = fminf(fmaxf(sm / 5.0f, 0.0f), 1.0f);
    }
}

// ---------------- prep duties (grid-stride; executed by rotrans' extra blocks) ------
// Bodies only execute when doneF/zeroBuf/demote fire; for this problem's input family
// (seq_dones == zeros, seq_update_global == ones) they never fire.
__device__ static void prep_body(float* out, float* buf, int t, int b,
                                 long long gid, long long stride) {
    if (g_st.doneF[b][t]) {
        float4 z = make_float4(0.f, 0.f, 0.f, 0.f);
        float4* gm4 = (float4*)(out + GMAP_OFF + (long long)b * CMAP * GG);
        for (long long i = gid; i < (long long)CMAP * GG / 4; i += stride) gm4[i] = z;
    }
    if (g_st.zeroBuf[b][t]) {
        float4 z = make_float4(0.f, 0.f, 0.f, 0.f);
        float4* bf4 = (float4*)(buf + (long long)b * CMAP * LL);
        for (long long i = gid; i < (long long)CMAP * LL / 4; i += stride) bf4[i] = z;
    }
    if (g_st.demote[b][t]) {
        int wr0 = g_st.wr0[b][t], wc0 = g_st.wc0[b][t];
        const float* gm = out + GMAP_OFF + (long long)b * CMAP * GG;
        float* bf = buf + (long long)b * CMAP * LL;
        for (long long e = gid; e < (long long)CMAP * LL; e += stride) {
            int c = (int)(e / LL); int rem = (int)(e % LL);
            int i = rem / LOCN, j = rem % LOCN;
            bf[e] = gm[(long long)c * GG + (long long)(wr0 + i) * GLON + (wc0 + j)];
        }
    }
}

// ---------------- fused rotate+translate+max-fuse+markers (+prep blocks) ------------
__device__ __forceinline__ bool rot_sample(int b, int t, int i2, int j2, float* rk) {
    const float step = 2.0f / 479.0f;
    float gx = -1.0f + (float)j2 * step;
    float gy = -1.0f + (float)i2 * step;
    float ct = g_st.ct[b][t], sn = g_st.snt[b][t];
    float gX = ct * gx + (-sn) * gy;
    float gY = sn * gx + ct * gy;
    float x = ((gX + 1.0f) * 479.0f) / 2.0f;
    float y = ((gY + 1.0f) * 479.0f) / 2.0f;
    if (x < 188.5f || x >= 290.5f || y < 238.5f || y >= 340.5f) return false;
    float x0 = floorf(x), y0 = floorf(y);
    const float* aw = g_avwin[b*TT + t];
    #pragma unroll
    for (int m = 0; m < 4; m++) {
        float xi = x0 + (float)(m & 1);
        float yi = y0 + (float)(m >> 1);
        if (!(xi >= 0.0f && xi <= 479.0f && yi >= 0.0f && yi <= 479.0f)) continue;
        int xii = (int)xi, yii = (int)yi;
        if (yii < 240 || yii > 339 || xii < 190 || xii > 289) continue;
        float wg = (1.0f - fabsf(x - xi)) * (1.0f - fabsf(y - yi));
        const float* row = aw + ((yii - 240) * VRN + (xii - 190)) * AVP;
        float4 v0 = *(const float4*)(row);
        float4 v1 = *(const float4*)(row + 4);
        float4 v2 = *(const float4*)(row + 8);
        float4 v3 = *(const float4*)(row + 12);
        float2 v4 = *(const float2*)(row + 16);
        rk[0]  += v0.x*wg; rk[1]  += v0.y*wg; rk[2]  += v0.z*wg; rk[3]  += v0.w*wg;
        rk[4]  += v1.x*wg; rk[5]  += v1.y*wg; rk[6]  += v1.z*wg; rk[7]  += v1.w*wg;
        rk[8]  += v2.x*wg; rk[9]  += v2.y*wg; rk[10] += v2.z*wg; rk[11] += v2.w*wg;
        rk[12] += v3.x*wg; rk[13] += v3.y*wg; rk[14] += v3.z*wg; rk[15] += v3.w*wg;
        rk[16] += v4.x*wg; rk[17] += v4.y*wg;
    }
    return true;
}

__global__ __launch_bounds__(256) void k_rotrans(float* out, float* buf, int t, int b) {
    if (blockIdx.x >= 900) {   // prep blocks (no-op unless rare flags fire)
        long long gid = (long long)(blockIdx.x - 900) * 256 + threadIdx.x;
        prep_body(out, buf, t, b, gid, 32LL * 256);
        return;
    }
    int ij = blockIdx.x * 256 + threadIdx.x;
    int i = ij / LOCN, j = ij % LOCN;
    int m = g_st.updMode[b][t];
    float* tgt; long long cs; int rs;
    if (m) {
        tgt = out + GMAP_OFF + (long long)b * CMAP * GG
              + (long long)g_st.wr0[b][t] * GLON + g_st.wc0[b][t];
        cs = GG; rs = GLON;
    } else {
        tgt = buf + (long long)b * CMAP * LL;
        cs = LL; rs = LOCN;
    }
    long long pix = (long long)i * rs + j;

    const float step = 2.0f / 479.0f;
    float gx = (-1.0f + (float)j * step) + g_st.stx[b][t];
    float gy = (-1.0f + (float)i * step) + g_st.sty[b][t];
    float x = ((gx + 1.0f) * 479.0f) / 2.0f;
    float y = ((gy + 1.0f) * 479.0f) / 2.0f;
    float x0 = floorf(x), y0 = floorf(y);
    float tr[18];
    #pragma unroll
    for (int s = 0; s < 18; s++) tr[s] = 0.0f;
    bool any = false;
    #pragma unroll
    for (int k = 0; k < 4; k++) {
        float xi = x0 + (float)(k & 1);
        float yi = y0 + (float)(k >> 1);
        if (!(xi >= 0.0f && xi <= 479.0f && yi >= 0.0f && yi <= 479.0f)) continue;
        float wg = (1.0f - fabsf(x - xi)) * (1.0f - fabsf(y - yi));
        float rk[18];
        #pragma unroll
        for (int s = 0; s < 18; s++) rk[s] = 0.0f;
        if (rot_sample(b, t, (int)yi, (int)xi, rk)) {
            any = true;
            #pragma unroll
            for (int s = 0; s < 18; s++) tr[s] += rk[s] * wg;
        }
    }
    int dr = i - g_st.yg[b][t];
    int dc = j - g_st.xg[b][t];
    tgt[2*cs + pix] = (abs(dr) <= 2 && abs(dc) <= 2) ? 1.0f : 0.0f;
    float disk = ((dr*dr + dc*dc) <= 1600) ? 1.0f : 0.0f;
    if (any) {
        g_cur0[b][ij] = fmaxf(tgt[pix], tr[0]);
        tgt[1*cs + pix] = fmaxf(tgt[1*cs + pix], tr[1]);
        tgt[3*cs + pix] = fmaxf(tgt[3*cs + pix], disk);
        #pragma unroll
        for (int c = 4; c < CMAP; c++)
            tgt[(long long)c*cs + pix] = fmaxf(tgt[(long long)c*cs + pix], tr[c - 2]);
    } else {
        g_cur0[b][ij] = tgt[pix];
        if (disk != 0.0f)
            tgt[3*cs + pix] = fmaxf(tgt[3*cs + pix], disk);
    }
}

// ---------------- fused dilate + optional slice write + feats (+final lmap) --------
__device__ __forceinline__ float dil0(int b, int i, int j) {
    float s = 0.f;
    #pragma unroll
    for (int di = -1; di <= 1; di++) {
        int ii = i + di;
        if (ii < 0 || ii >= LOCN) continue;
        #pragma unroll
        for (int dj = -1; dj <= 1; dj++) {
            int jj = j + dj;
            if (jj < 0 || jj >= LOCN) continue;
            s += g_cur0[b][ii * LOCN + jj];
        }
    }
    return (s > 0.5f) ? 1.0f : 0.0f;
}

__global__ __launch_bounds__(256) void k_gupfeats(float* out, float* buf, int t, int b, int last) {
    int ij = blockIdx.x * 256 + threadIdx.x;
    int i = ij / LOCN, j = ij % LOCN;
    int m = g_st.updMode[b][t];
    bool u = g_st.updg[b][t] != 0;
    bool sw = g_st.sliceW[b][t] != 0;
    int wr0 = g_st.wr0[b][t], wc0 = g_st.wc0[b][t];
    int nr0 = g_st.nr0[b][t], nc0 = g_st.nc0[b][t];
    float* gm = out + GMAP_OFF + (long long)b * CMAP * GG;
    float* bf = buf + (long long)b * CMAP * LL;
    float* tgt; long long cs; int rs;
    if (m) { tgt = gm + (long long)wr0 * GLON + wc0; cs = GG; rs = GLON; }
    else   { tgt = bf; cs = LL; rs = LOCN; }
    long long pix = (long long)i * rs + j;

    float d0 = dil0(b, i, j);
    tgt[pix] = d0;
    if (sw) {
        long long gw = (long long)(wr0 + i) * GLON + (wc0 + j);
        gm[gw] = d0;
        #pragma unroll
        for (int c = 1; c < CMAP; c++)
            gm[(long long)c * GG + gw] = bf[(long long)c * LL + ij];
    }

    auto eff = [&](int c, int r, int cc) -> float {
        if (u && r >= wr0 && r < wr0 + LOCN && cc >= wc0 && cc < wc0 + LOCN) {
            int li = r - wr0, lj = cc - wc0;
            if (c == 0) return dil0(b, li, lj);
            if (m == 0) return bf[(long long)c * LL + li * LOCN + lj];
        }
        return gm[(long long)c * GG + (long long)r * GLON + cc];
    };

    float lv[CMAP];
    if (u) {
        #pragma unroll
        for (int c = 0; c < CMAP; c++) lv[c] = eff(c, nr0 + i, nc0 + j);
    } else {
        lv[0] = d0;
        #pragma unroll
        for (int c = 1; c < CMAP; c++) lv[c] = tgt[(long long)c * cs + pix];
    }
    float gd[4];
    #pragma unroll
    for (int c = 0; c < 4; c++) {
        if ((m == 1 && c >= 1) || !u) {
            const float* gb = gm + (long long)c * GG + (long long)(2*i) * GLON + 2*j;
            float2 r0 = *(const float2*)gb;
            float2 r1 = *(const float2*)(gb + GLON);
            gd[c] = fmaxf(fmaxf(r0.x, r0.y), fmaxf(r1.x, r1.y));
        } else {
            float a0 = eff(c, 2*i, 2*j),     a1 = eff(c, 2*i, 2*j + 1);
            float a2 = eff(c, 2*i + 1, 2*j), a3 = eff(c, 2*i + 1, 2*j + 1);
            gd[c] = fmaxf(fmaxf(a0, a1), fmaxf(a2, a3));
        }
    }
    float* fe = out + FE_OFF + (long long)(b*TT + t) * 24 * LL + ij;
    fe[0] = lv[0];
    fe[(long long)1*LL] = lv[1];
    fe[(long long)2*LL] = lv[2];
    fe[(long long)3*LL] = lv[3];
    #pragma unroll
    for (int c = 0; c < 4; c++) fe[(long long)(4 + c) * LL] = gd[c];
    #pragma unroll
    for (int c = 0; c < NSEM; c++) fe[(long long)(8 + c) * LL] = lv[4 + c];

    if (last) {
        float* lo = out + LMAP_OFF + (long long)b * CMAP * LL + ij;
        #pragma unroll
        for (int c = 0; c < CMAP; c++) lo[(long long)c * LL] = lv[c];
    }
}

// ---------------- launcher ----------------
extern "C" void kernel_launch(void* const* d_in, const int* in_sizes, int n_in,
                              void* d_out, int out_size) {
    const float* obs  = (const float*)d_in[0];
    const float* pd   = (const float*)d_in[1];
    const void*  dn   = d_in[2];
    const void*  ug   = d_in[3];
    // d_in[4]: seq_camera_poses (unused)
    const float* ilm  = (const float*)d_in[5];
    const float* igm  = (const float*)d_in[6];
    const float* ilp  = (const float*)d_in[7];
    const float* igp  = (const float*)d_in[8];
    const int*   ilmb = (const int*)d_in[9];
    const float* iog  = (const float*)d_in[10];
    float* out = (float*)d_out;
    float focal = (float)(320.0 / tan(39.5 * M_PI / 180.0));

    float* lmA; cudaGetSymbolAddress((void**)&lmA, g_lmA);

    // streams: s2 = voxel pipeline (+ deferred re-zero), s3 = b=1 chain.
    cudaStream_t s2, s3;
    cudaStreamCreateWithFlags(&s2, cudaStreamNonBlocking);
    cudaStreamCreateWithFlags(&s3, cudaStreamNonBlocking);
    cudaEvent_t eFork, eJoin, eZero, eReady, eB1;
    cudaEventCreateWithFlags(&eFork, cudaEventDisableTiming);
    cudaEventCreateWithFlags(&eJoin, cudaEventDisableTiming);
    cudaEventCreateWithFlags(&eZero, cudaEventDisableTiming);
    cudaEventCreateWithFlags(&eReady, cudaEventDisableTiming);
    cudaEventCreateWithFlags(&eB1, cudaEventDisableTiming);

    cudaEventRecord(eFork, 0);
    cudaStreamWaitEvent(s2, eFork, 0);
    k_pointsplat_all<<<9600, 256, 0, s2>>>(obs, focal);
    k_heights_all<<<5313, 256, 0, s2>>>();
    cudaEventRecord(eJoin, s2);
    k_zvox_all<<<21250, 256, 0, s2>>>();          // restore zero invariant, off critical path
    cudaEventRecord(eZero, s2);

    k_init<<<1, BB>>>(ilp, igp, ilmb, iog, dn, ug, pd, out);
    cudaMemcpyAsync(lmA, ilm, (size_t)BB * CMAP * LL * sizeof(float),
                    cudaMemcpyDeviceToDevice);
    cudaMemcpyAsync(out + GMAP_OFF, igm, (size_t)BB * CMAP * GG * sizeof(float),
                    cudaMemcpyDeviceToDevice);

    cudaStreamWaitEvent(0, eJoin, 0);
    cudaEventRecord(eReady, 0);                    // init+copies+heights all done
    cudaStreamWaitEvent(s3, eReady, 0);

    // independent per-batch chains: b=0 on stream 0, b=1 on s3
    for (int t = 0; t < TT; t++) {
        k_rotrans<<<932, 256, 0, 0>>>(out, lmA, t, 0);
        k_gupfeats<<<900, 256, 0, 0>>>(out, lmA, t, 0, t == TT-1 ? 1 : 0);
        k_rotrans<<<932, 256, 0, s3>>>(out, lmA, t, 1);
        k_gupfeats<<<900, 256, 0, s3>>>(out, lmA, t, 1, t == TT-1 ? 1 : 0);
    }
    cudaEventRecord(eB1, s3);
    cudaStreamWaitEvent(0, eB1, 0);
    cudaStreamWaitEvent(0, eZero, 0);             // graph ends only after re-zero

    cudaEventDestroy(eFork);
    cudaEventDestroy(eJoin);
    cudaEventDestroy(eZero);
    cudaEventDestroy(eReady);
    cudaEventDestroy(eB1);
    cudaStreamDestroy(s2);
    cudaStreamDestroy(s3);
}